// round 15
// baseline (speedup 1.0000x reference)
#include <cuda_runtime.h>
#include <math.h>

// Problem constants (B=4, S=2048, D_IN=1024, D_OUT=1024, E=8, K=2)
#define BTOK    8192
#define DIN     1024
#define DOUT    1024
#define NE      8
#define SPLITK  8
#define KSPAN   (DIN / SPLITK)   // 128 k per split
#define CH      16               // k per pipelined chunk
#define NCH     (KSPAN / CH)     // 8
#define TM      256              // tokens per K1 block (4 warps x 64 tokens)
#define TPB     128
#define XST     20               // xs token-row stride (floats); 80B rows

// Gate partials: g_gate[token*64 + split*8 + row]  (2 MB)
__device__ float g_gate[BTOK * SPLITK * NE];

__device__ __forceinline__ unsigned long long fma2(unsigned long long a,
                                                   unsigned long long b,
                                                   unsigned long long c) {
    unsigned long long d;
    asm("fma.rn.f32x2 %0, %1, %2, %3;" : "=l"(d) : "l"(a), "l"(b), "l"(c));
    return d;
}
__device__ __forceinline__ void unpack2(unsigned long long v, float& lo, float& hi) {
    asm("mov.b64 {%0, %1}, %2;" : "=f"(lo), "=f"(hi) : "l"(v));
}
#define CP_ASYNC16(dst_u32, src_ptr) \
    asm volatile("cp.async.cg.shared.global [%0], [%1], 16;" \
                 :: "r"(dst_u32), "l"(src_ptr))
#define CP_COMMIT() asm volatile("cp.async.commit_group;" ::: "memory")
#define CP_WAIT(n)  asm volatile("cp.async.wait_group %0;" :: "n"(n) : "memory")

// ---------------------------------------------------------------------------
// Kernel 1: gate GEMM only (8 rows). Split-K 8, cp.async double-buffered x,
// warp = 8 rows x 64 tokens (2 tok/thread: lane & lane+32), FFMA2.
// (identical to R14 winner)
// ---------------------------------------------------------------------------
__global__ __launch_bounds__(TPB)
void gate_gemm_kernel(const float* __restrict__ x,
                      const float* __restrict__ gate_w)
{
    __shared__ float xs[2][TM][XST];     // 40960 B
    __shared__ float ws[NE][132];        // 4224 B

    const int tid   = threadIdx.x;
    const int split = blockIdx.x & (SPLITK - 1);
    const int grp   = blockIdx.x >> 3;
    const int tok0  = grp * TM;
    const int kbase = split * KSPAN;
    const int wid   = tid >> 5;
    const int lane  = tid & 31;
    const int tkoff = wid * 64 + lane;      // tokens tkoff, tkoff+32 (in block)

    // ---- issue x chunk 0: 256 tok x 16 k = 1024 float4, 8/thread ----
    #pragma unroll
    for (int j = 0; j < 8; j++) {
        int i = tid + j * TPB;
        int m = i >> 2;
        int f = (i & 3) << 2;
        unsigned dst = (unsigned)__cvta_generic_to_shared(&xs[0][m][f]);
        CP_ASYNC16(dst, x + (size_t)(tok0 + m) * DIN + kbase + f);
    }
    CP_COMMIT();

    // ---- gate weights: 8 rows x 128 floats = 256 float4, 2/thread ----
    #pragma unroll
    for (int j = 0; j < 2; j++) {
        int i   = tid + j * TPB;
        int row = i >> 5;
        int f4  = (i & 31) << 2;
        float4 v = *(const float4*)(gate_w + (size_t)row * DIN + kbase + f4);
        *(float4*)&ws[row][f4] = v;
    }

    unsigned long long acc0[NE], acc1[NE];
    #pragma unroll
    for (int r = 0; r < NE; r++) { acc0[r] = 0ULL; acc1[r] = 0ULL; }

    #pragma unroll
    for (int c = 0; c < NCH; c++) {
        const int buf = c & 1;
        if (c + 1 < NCH) {
            const int nk = kbase + (c + 1) * CH;
            #pragma unroll
            for (int j = 0; j < 8; j++) {
                int i = tid + j * TPB;
                int m = i >> 2;
                int f = (i & 3) << 2;
                unsigned dst = (unsigned)__cvta_generic_to_shared(&xs[buf ^ 1][m][f]);
                CP_ASYNC16(dst, x + (size_t)(tok0 + m) * DIN + nk + f);
            }
            CP_COMMIT();
            CP_WAIT(1);
        } else {
            CP_WAIT(0);
        }
        __syncthreads();

        const float* xr0 = &xs[buf][tkoff][0];
        const float* xr1 = &xs[buf][tkoff + 32][0];
        #pragma unroll
        for (int q = 0; q < 4; q++) {
            ulonglong2 xa = *(const ulonglong2*)(xr0 + q * 4);
            ulonglong2 xb = *(const ulonglong2*)(xr1 + q * 4);
            const int kk = c * CH + q * 4;
            #pragma unroll
            for (int r = 0; r < NE; r++) {
                ulonglong2 wv = *(const ulonglong2*)(&ws[r][kk]);   // broadcast
                acc0[r] = fma2(xa.x, wv.x, acc0[r]);
                acc0[r] = fma2(xa.y, wv.y, acc0[r]);
                acc1[r] = fma2(xb.x, wv.x, acc1[r]);
                acc1[r] = fma2(xb.y, wv.y, acc1[r]);
            }
        }
        __syncthreads();
    }

    // ---- store gate partials: g_gate[token*64 + split*8 + row] ----
    {
        float s[NE];
        #pragma unroll
        for (int r = 0; r < NE; r++) {
            float lo, hi; unpack2(acc0[r], lo, hi); s[r] = lo + hi;
        }
        float4* dst = (float4*)(g_gate + (size_t)(tok0 + tkoff) * 64 + split * 8);
        dst[0] = make_float4(s[0], s[1], s[2], s[3]);
        dst[1] = make_float4(s[4], s[5], s[6], s[7]);
    }
    {
        float s[NE];
        #pragma unroll
        for (int r = 0; r < NE; r++) {
            float lo, hi; unpack2(acc1[r], lo, hi); s[r] = lo + hi;
        }
        float4* dst = (float4*)(g_gate + (size_t)(tok0 + tkoff + 32) * 64 + split * 8);
        dst[0] = make_float4(s[0], s[1], s[2], s[3]);
        dst[1] = make_float4(s[4], s[5], s[6], s[7]);
    }
}

// ---------------------------------------------------------------------------
// Kernel 2: warp-per-token — x prefetched to registers, gate reduce + top-2
// overlapped with x latency, then 2 expert dots + broadcast write.
// ---------------------------------------------------------------------------
__global__ __launch_bounds__(256)
void moe_out_kernel(const float* __restrict__ x,
                    const float* __restrict__ gate_b,
                    const float* __restrict__ ebias,
                    const float* __restrict__ expert_w,
                    const float* __restrict__ expert_b,
                    float* __restrict__ out,
                    float* __restrict__ idx_out)
{
    __shared__ float gbias[NE];
    const int tid  = threadIdx.x;
    const int wid  = tid >> 5;
    const int lane = tid & 31;

    if (tid < NE) gbias[tid] = gate_b[tid] + ebias[tid];
    __syncthreads();

    const int token = blockIdx.x * 8 + wid;

    // ---- prefetch x into registers (8 float4, MLP=8) ----
    const float4* xv = (const float4*)(x + (size_t)token * DIN);
    float4 xx[8];
    #pragma unroll
    for (int j = 0; j < 8; j++)
        xx[j] = xv[j * 32 + lane];

    // ---- gate reduce (overlaps with x loads): 64 floats as float2 ----
    float2 g2 = *(const float2*)(g_gate + (size_t)token * 64 + lane * 2);
    #pragma unroll
    for (int off = 4; off <= 16; off <<= 1) {
        g2.x += __shfl_xor_sync(0xFFFFFFFFu, g2.x, off);
        g2.y += __shfl_xor_sync(0xFFFFFFFFu, g2.y, off);
    }
    float logit[NE];
    #pragma unroll
    for (int i = 0; i < 4; i++) {
        float lx = __shfl_sync(0xFFFFFFFFu, g2.x, i);
        float ly = __shfl_sync(0xFFFFFFFFu, g2.y, i);
        logit[2 * i]     = lx + gbias[2 * i];
        logit[2 * i + 1] = ly + gbias[2 * i + 1];
    }

    // ---- top-2, first-occurrence tie-break (warp-uniform) ----
    int e0 = 0; float b0 = logit[0];
    #pragma unroll
    for (int e = 1; e < NE; e++)
        if (logit[e] > b0) { b0 = logit[e]; e0 = e; }
    int e1 = -1; float b1 = -INFINITY;
    #pragma unroll
    for (int e = 0; e < NE; e++) {
        if (e == e0) continue;
        if (logit[e] > b1) { b1 = logit[e]; e1 = e; }
    }

    // ---- two expert dots against register-resident x ----
    const float4* w0 = (const float4*)(expert_w + ((size_t)e0 * DOUT + 0) * DIN);
    const float4* w1 = (const float4*)(expert_w + ((size_t)e1 * DOUT + 1) * DIN);
    float a0 = 0.f, a1 = 0.f;
    #pragma unroll
    for (int j = 0; j < 8; j++) {
        float4 u0 = w0[j * 32 + lane];
        float4 u1 = w1[j * 32 + lane];
        a0 = fmaf(xx[j].x, u0.x, a0); a0 = fmaf(xx[j].y, u0.y, a0);
        a0 = fmaf(xx[j].z, u0.z, a0); a0 = fmaf(xx[j].w, u0.w, a0);
        a1 = fmaf(xx[j].x, u1.x, a1); a1 = fmaf(xx[j].y, u1.y, a1);
        a1 = fmaf(xx[j].z, u1.z, a1); a1 = fmaf(xx[j].w, u1.w, a1);
    }
    #pragma unroll
    for (int off = 16; off > 0; off >>= 1) {
        a0 += __shfl_xor_sync(0xFFFFFFFFu, a0, off);
        a1 += __shfl_xor_sync(0xFFFFFFFFu, a1, off);
    }

    float v0 = a0 + expert_b[(size_t)e0 * DOUT + 0];
    float v1 = a1 + expert_b[(size_t)e1 * DOUT + 1];
    float p0 = 1.f / (1.f + expf(-b0));
    float p1 = 1.f / (1.f + expf(-b1));
    float wv = (v0 * p0 + v1 * p1) / (p0 + p1);

    if (idx_out && lane == 0) {
        idx_out[(size_t)token * 2 + 0] = (float)e0;
        idx_out[(size_t)token * 2 + 1] = (float)e1;
    }

    // ---- broadcast write: 1024 floats, 8 STG.128 per lane ----
    float4 v4 = make_float4(wv, wv, wv, wv);
    float4* orow = (float4*)(out + (size_t)token * DOUT);
    #pragma unroll
    for (int j = 0; j < 8; j++)
        orow[j * 32 + lane] = v4;
}

extern "C" void kernel_launch(void* const* d_in, const int* in_sizes, int n_in,
                              void* d_out, int out_size)
{
    const float* x        = (const float*)d_in[0];
    const float* gate_w   = (const float*)d_in[1];
    const float* gate_b   = (const float*)d_in[2];
    const float* ebias    = (const float*)d_in[3];
    const float* expert_w = (const float*)d_in[4];
    const float* expert_b = (const float*)d_in[5];
    float* out = (float*)d_out;

    float* idx_out = nullptr;
    long long base = (long long)BTOK * DOUT;
    if ((long long)out_size >= base + (long long)BTOK * 2)
        idx_out = out + base;

    gate_gemm_kernel<<<(BTOK / TM) * SPLITK, TPB>>>(x, gate_w);
    moe_out_kernel<<<BTOK / 8, 256>>>(x, gate_b, ebias, expert_w, expert_b,
                                      out, idx_out);
}

// round 16
// speedup vs baseline: 1.0040x; 1.0040x over previous
#include <cuda_runtime.h>
#include <math.h>

// Problem constants (B=4, S=2048, D_IN=1024, D_OUT=1024, E=8, K=2)
#define BTOK    8192
#define DIN     1024
#define DOUT    1024
#define NE      8
#define SPLITK  8
#define KSPAN   (DIN / SPLITK)   // 128 k per split
#define CH      16               // k per pipelined chunk
#define NCH     (KSPAN / CH)     // 8
#define TM      64               // tokens per K1 block (thread = token)
#define TPB     64
#define XST     20               // xs token-row stride; conflict-free 8-lane phases

// Gate partials: g_gate[token*64 + split*8 + row]  (2 MB)
__device__ float g_gate[BTOK * SPLITK * NE];

__device__ __forceinline__ unsigned long long fma2(unsigned long long a,
                                                   unsigned long long b,
                                                   unsigned long long c) {
    unsigned long long d;
    asm("fma.rn.f32x2 %0, %1, %2, %3;" : "=l"(d) : "l"(a), "l"(b), "l"(c));
    return d;
}
__device__ __forceinline__ void unpack2(unsigned long long v, float& lo, float& hi) {
    asm("mov.b64 {%0, %1}, %2;" : "=f"(lo), "=f"(hi) : "l"(v));
}
#define CP_ASYNC16(dst_u32, src_ptr) \
    asm volatile("cp.async.cg.shared.global [%0], [%1], 16;" \
                 :: "r"(dst_u32), "l"(src_ptr))
#define CP_COMMIT() asm volatile("cp.async.commit_group;" ::: "memory")
#define CP_WAIT(n)  asm volatile("cp.async.wait_group %0;" :: "n"(n) : "memory")

// ---------------------------------------------------------------------------
// Kernel 1: gate GEMM (8 rows). Split-K 8, grid 1024 (64 tokens/block),
// thread = token, cp.async double-buffered x, broadcast w, FFMA2.
// ---------------------------------------------------------------------------
__global__ __launch_bounds__(TPB)
void gate_gemm_kernel(const float* __restrict__ x,
                      const float* __restrict__ gate_w)
{
    __shared__ float xs[2][TM][XST];     // 10240 B
    __shared__ float ws[NE][132];        // 4224 B

    const int tid   = threadIdx.x;
    const int split = blockIdx.x & (SPLITK - 1);
    const int grp   = blockIdx.x >> 3;
    const int tok0  = grp * TM;
    const int kbase = split * KSPAN;
    const int token = tok0 + tid;

    // ---- issue x chunk 0: 64 tok x 16 k = 256 float4, 4/thread ----
    #pragma unroll
    for (int j = 0; j < 4; j++) {
        int i = tid + j * TPB;
        int m = i >> 2;
        int f = (i & 3) << 2;
        unsigned dst = (unsigned)__cvta_generic_to_shared(&xs[0][m][f]);
        CP_ASYNC16(dst, x + (size_t)(tok0 + m) * DIN + kbase + f);
    }
    CP_COMMIT();

    // ---- gate weights: 8 rows x 128 floats = 256 float4, 4/thread ----
    #pragma unroll
    for (int j = 0; j < 4; j++) {
        int i   = tid + j * TPB;
        int row = i >> 5;
        int f4  = (i & 31) << 2;
        float4 v = *(const float4*)(gate_w + (size_t)row * DIN + kbase + f4);
        *(float4*)&ws[row][f4] = v;
    }

    unsigned long long acc[NE];
    #pragma unroll
    for (int r = 0; r < NE; r++) acc[r] = 0ULL;

    #pragma unroll
    for (int c = 0; c < NCH; c++) {
        const int buf = c & 1;
        if (c + 1 < NCH) {
            const int nk = kbase + (c + 1) * CH;
            #pragma unroll
            for (int j = 0; j < 4; j++) {
                int i = tid + j * TPB;
                int m = i >> 2;
                int f = (i & 3) << 2;
                unsigned dst = (unsigned)__cvta_generic_to_shared(&xs[buf ^ 1][m][f]);
                CP_ASYNC16(dst, x + (size_t)(tok0 + m) * DIN + nk + f);
            }
            CP_COMMIT();
            CP_WAIT(1);
        } else {
            CP_WAIT(0);
        }
        __syncthreads();

        const float* xr = &xs[buf][tid][0];
        #pragma unroll
        for (int q = 0; q < 4; q++) {
            ulonglong2 xv = *(const ulonglong2*)(xr + q * 4);
            const int kk = c * CH + q * 4;
            #pragma unroll
            for (int r = 0; r < NE; r++) {
                ulonglong2 wv = *(const ulonglong2*)(&ws[r][kk]);   // broadcast
                acc[r] = fma2(xv.x, wv.x, acc[r]);
                acc[r] = fma2(xv.y, wv.y, acc[r]);
            }
        }
        __syncthreads();
    }

    // ---- store gate partials: g_gate[token*64 + split*8 + row] ----
    {
        float s[NE];
        #pragma unroll
        for (int r = 0; r < NE; r++) {
            float lo, hi; unpack2(acc[r], lo, hi); s[r] = lo + hi;
        }
        float4* dst = (float4*)(g_gate + (size_t)token * 64 + split * 8);
        dst[0] = make_float4(s[0], s[1], s[2], s[3]);
        dst[1] = make_float4(s[4], s[5], s[6], s[7]);
    }
}

// ---------------------------------------------------------------------------
// Kernel 2: warp-per-token (identical to R15) — x prefetch to regs, gate
// reduce + top-2 overlapped, 2 expert dots, broadcast write.
// ---------------------------------------------------------------------------
__global__ __launch_bounds__(256)
void moe_out_kernel(const float* __restrict__ x,
                    const float* __restrict__ gate_b,
                    const float* __restrict__ ebias,
                    const float* __restrict__ expert_w,
                    const float* __restrict__ expert_b,
                    float* __restrict__ out,
                    float* __restrict__ idx_out)
{
    __shared__ float gbias[NE];
    const int tid  = threadIdx.x;
    const int wid  = tid >> 5;
    const int lane = tid & 31;

    if (tid < NE) gbias[tid] = gate_b[tid] + ebias[tid];
    __syncthreads();

    const int token = blockIdx.x * 8 + wid;

    // ---- prefetch x into registers (8 float4, MLP=8) ----
    const float4* xv = (const float4*)(x + (size_t)token * DIN);
    float4 xx[8];
    #pragma unroll
    for (int j = 0; j < 8; j++)
        xx[j] = xv[j * 32 + lane];

    // ---- gate reduce (overlaps x loads): 64 floats as float2/lane ----
    float2 g2 = *(const float2*)(g_gate + (size_t)token * 64 + lane * 2);
    #pragma unroll
    for (int off = 4; off <= 16; off <<= 1) {
        g2.x += __shfl_xor_sync(0xFFFFFFFFu, g2.x, off);
        g2.y += __shfl_xor_sync(0xFFFFFFFFu, g2.y, off);
    }
    float logit[NE];
    #pragma unroll
    for (int i = 0; i < 4; i++) {
        float lx = __shfl_sync(0xFFFFFFFFu, g2.x, i);
        float ly = __shfl_sync(0xFFFFFFFFu, g2.y, i);
        logit[2 * i]     = lx + gbias[2 * i];
        logit[2 * i + 1] = ly + gbias[2 * i + 1];
    }

    // ---- top-2, first-occurrence tie-break (warp-uniform) ----
    int e0 = 0; float b0 = logit[0];
    #pragma unroll
    for (int e = 1; e < NE; e++)
        if (logit[e] > b0) { b0 = logit[e]; e0 = e; }
    int e1 = -1; float b1 = -INFINITY;
    #pragma unroll
    for (int e = 0; e < NE; e++) {
        if (e == e0) continue;
        if (logit[e] > b1) { b1 = logit[e]; e1 = e; }
    }

    // ---- two expert dots against register-resident x ----
    const float4* w0 = (const float4*)(expert_w + ((size_t)e0 * DOUT + 0) * DIN);
    const float4* w1 = (const float4*)(expert_w + ((size_t)e1 * DOUT + 1) * DIN);
    float a0 = 0.f, a1 = 0.f;
    #pragma unroll
    for (int j = 0; j < 8; j++) {
        float4 u0 = w0[j * 32 + lane];
        float4 u1 = w1[j * 32 + lane];
        a0 = fmaf(xx[j].x, u0.x, a0); a0 = fmaf(xx[j].y, u0.y, a0);
        a0 = fmaf(xx[j].z, u0.z, a0); a0 = fmaf(xx[j].w, u0.w, a0);
        a1 = fmaf(xx[j].x, u1.x, a1); a1 = fmaf(xx[j].y, u1.y, a1);
        a1 = fmaf(xx[j].z, u1.z, a1); a1 = fmaf(xx[j].w, u1.w, a1);
    }
    #pragma unroll
    for (int off = 16; off > 0; off >>= 1) {
        a0 += __shfl_xor_sync(0xFFFFFFFFu, a0, off);
        a1 += __shfl_xor_sync(0xFFFFFFFFu, a1, off);
    }

    float v0 = a0 + expert_b[(size_t)e0 * DOUT + 0];
    float v1 = a1 + expert_b[(size_t)e1 * DOUT + 1];
    float p0 = 1.f / (1.f + expf(-b0));
    float p1 = 1.f / (1.f + expf(-b1));
    float wv = (v0 * p0 + v1 * p1) / (p0 + p1);

    if (idx_out && lane == 0) {
        idx_out[(size_t)token * 2 + 0] = (float)e0;
        idx_out[(size_t)token * 2 + 1] = (float)e1;
    }

    // ---- broadcast write: 1024 floats, 8 STG.128 per lane ----
    float4 v4 = make_float4(wv, wv, wv, wv);
    float4* orow = (float4*)(out + (size_t)token * DOUT);
    #pragma unroll
    for (int j = 0; j < 8; j++)
        orow[j * 32 + lane] = v4;
}

extern "C" void kernel_launch(void* const* d_in, const int* in_sizes, int n_in,
                              void* d_out, int out_size)
{
    const float* x        = (const float*)d_in[0];
    const float* gate_w   = (const float*)d_in[1];
    const float* gate_b   = (const float*)d_in[2];
    const float* ebias    = (const float*)d_in[3];
    const float* expert_w = (const float*)d_in[4];
    const float* expert_b = (const float*)d_in[5];
    float* out = (float*)d_out;

    float* idx_out = nullptr;
    long long base = (long long)BTOK * DOUT;
    if ((long long)out_size >= base + (long long)BTOK * 2)
        idx_out = out + base;

    gate_gemm_kernel<<<(BTOK / TM) * SPLITK, TPB>>>(x, gate_w);
    moe_out_kernel<<<BTOK / 8, 256>>>(x, gate_b, ebias, expert_w, expert_b,
                                      out, idx_out);
}

// round 17
// speedup vs baseline: 1.0500x; 1.0458x over previous
#include <cuda_runtime.h>
#include <math.h>

// Problem constants (B=4, S=2048, D_IN=1024, D_OUT=1024, E=8, K=2)
#define BTOK   8192
#define DIN    1024
#define DOUT   1024
#define NE     8

// ---------------------------------------------------------------------------
// Single fused kernel: warp-per-token.
//   - prefetch x row to registers (8 float4/lane)
//   - 8 gate dots straight from gate_w (L1-hot), 8 independent FMA chains
//   - butterfly reduce, warp-uniform top-2
//   - 2 expert dots against register x
//   - sigmoid combine, broadcast 1024-float write
// ---------------------------------------------------------------------------
__global__ __launch_bounds__(128)
void moe_fused_kernel(const float* __restrict__ x,
                      const float* __restrict__ gate_w,
                      const float* __restrict__ gate_b,
                      const float* __restrict__ ebias,
                      const float* __restrict__ expert_w,
                      const float* __restrict__ expert_b,
                      float* __restrict__ out,
                      float* __restrict__ idx_out)
{
    __shared__ float gbias[NE];
    const int tid  = threadIdx.x;
    const int wid  = tid >> 5;
    const int lane = tid & 31;

    if (tid < NE) gbias[tid] = gate_b[tid] + ebias[tid];
    __syncthreads();

    const int token = blockIdx.x * 4 + wid;

    // ---- prefetch x row into registers: 8 float4/lane, MLP=8 ----
    const float4* xv = (const float4*)(x + (size_t)token * DIN);
    float4 xx[8];
    #pragma unroll
    for (int j = 0; j < 8; j++)
        xx[j] = xv[j * 32 + lane];

    // ---- 8 gate dots: 8 independent accumulator chains ----
    float ga[NE];
    #pragma unroll
    for (int r = 0; r < NE; r++) ga[r] = 0.f;

    #pragma unroll
    for (int r = 0; r < NE; r++) {
        const float4* wr = (const float4*)(gate_w + (size_t)r * DIN);
        float a = 0.f;
        #pragma unroll
        for (int j = 0; j < 8; j++) {
            float4 u = wr[j * 32 + lane];          // L1-hot (same across warps)
            a = fmaf(xx[j].x, u.x, a);
            a = fmaf(xx[j].y, u.y, a);
            a = fmaf(xx[j].z, u.z, a);
            a = fmaf(xx[j].w, u.w, a);
        }
        ga[r] = a;
    }

    // ---- butterfly reduce all 8 sums (independent, pipelined) ----
    #pragma unroll
    for (int off = 16; off > 0; off >>= 1) {
        #pragma unroll
        for (int r = 0; r < NE; r++)
            ga[r] += __shfl_xor_sync(0xFFFFFFFFu, ga[r], off);
    }

    float logit[NE];
    #pragma unroll
    for (int r = 0; r < NE; r++)
        logit[r] = ga[r] + gbias[r];

    // ---- top-2, first-occurrence tie-break (warp-uniform) ----
    int e0 = 0; float b0 = logit[0];
    #pragma unroll
    for (int e = 1; e < NE; e++)
        if (logit[e] > b0) { b0 = logit[e]; e0 = e; }
    int e1 = -1; float b1 = -INFINITY;
    #pragma unroll
    for (int e = 0; e < NE; e++) {
        if (e == e0) continue;
        if (logit[e] > b1) { b1 = logit[e]; e1 = e; }
    }

    // ---- two expert dots against register-resident x ----
    const float4* w0 = (const float4*)(expert_w + ((size_t)e0 * DOUT + 0) * DIN);
    const float4* w1 = (const float4*)(expert_w + ((size_t)e1 * DOUT + 1) * DIN);
    float a0 = 0.f, a1 = 0.f;
    #pragma unroll
    for (int j = 0; j < 8; j++) {
        float4 u0 = w0[j * 32 + lane];
        float4 u1 = w1[j * 32 + lane];
        a0 = fmaf(xx[j].x, u0.x, a0); a0 = fmaf(xx[j].y, u0.y, a0);
        a0 = fmaf(xx[j].z, u0.z, a0); a0 = fmaf(xx[j].w, u0.w, a0);
        a1 = fmaf(xx[j].x, u1.x, a1); a1 = fmaf(xx[j].y, u1.y, a1);
        a1 = fmaf(xx[j].z, u1.z, a1); a1 = fmaf(xx[j].w, u1.w, a1);
    }
    #pragma unroll
    for (int off = 16; off > 0; off >>= 1) {
        a0 += __shfl_xor_sync(0xFFFFFFFFu, a0, off);
        a1 += __shfl_xor_sync(0xFFFFFFFFu, a1, off);
    }

    float v0 = a0 + expert_b[(size_t)e0 * DOUT + 0];
    float v1 = a1 + expert_b[(size_t)e1 * DOUT + 1];
    float p0 = 1.f / (1.f + expf(-b0));
    float p1 = 1.f / (1.f + expf(-b1));
    float wv = (v0 * p0 + v1 * p1) / (p0 + p1);

    if (idx_out && lane == 0) {
        idx_out[(size_t)token * 2 + 0] = (float)e0;
        idx_out[(size_t)token * 2 + 1] = (float)e1;
    }

    // ---- broadcast write: 1024 floats, 8 STG.128 per lane ----
    float4 v4 = make_float4(wv, wv, wv, wv);
    float4* orow = (float4*)(out + (size_t)token * DOUT);
    #pragma unroll
    for (int j = 0; j < 8; j++)
        orow[j * 32 + lane] = v4;
}

extern "C" void kernel_launch(void* const* d_in, const int* in_sizes, int n_in,
                              void* d_out, int out_size)
{
    const float* x        = (const float*)d_in[0];
    const float* gate_w   = (const float*)d_in[1];
    const float* gate_b   = (const float*)d_in[2];
    const float* ebias    = (const float*)d_in[3];
    const float* expert_w = (const float*)d_in[4];
    const float* expert_b = (const float*)d_in[5];
    float* out = (float*)d_out;

    float* idx_out = nullptr;
    long long base = (long long)BTOK * DOUT;
    if ((long long)out_size >= base + (long long)BTOK * 2)
        idx_out = out + base;

    moe_fused_kernel<<<BTOK / 4, 128>>>(x, gate_w, gate_b, ebias,
                                        expert_w, expert_b, out, idx_out);
}